// round 10
// baseline (speedup 1.0000x reference)
#include <cuda_runtime.h>
#include <cuda_fp16.h>
#include <math_constants.h>

#define NN 50000
#define EE 1600000
#define DD 128
#define NEG_SLOPE 0.01f
#define SCAN_B 256
#define NBLK ((NN + SCAN_B - 1) / SCAN_B)   // 196

// Scratch (__device__ globals; no allocation allowed)
__device__ int   g_deg[NN];
__device__ int   g_off[NN + 1];
__device__ int   g_curp[NN];
__device__ int   g_bsum[NBLK];
__device__ int   g_boff[NBLK];
__device__ int2  g_ew[EE];          // (.x = src | dst<<16, .y = exp-weight bits), dst-sorted
__device__ uint2 g_hA[NN * 32];     // fp16x4 per lane: layer-0 gather source
__device__ uint2 g_hB[NN * 32];     // fp16x4 per lane: layer-1 gather source (mid)
__device__ float g_ssrc[NN];
__device__ float g_sdst[NN];

// ---------------- build ---------------------------------------------------------

// 4-edge-per-thread histogram: batched int4 load -> 4 independent atomics (MLP=4).
__global__ void k_hist4(const int* __restrict__ dst, int e) {
    int i = (blockIdx.x * blockDim.x + threadIdx.x) * 4;
    if (i + 3 < e) {
        int4 d4 = *(const int4*)(dst + i);
        atomicAdd(&g_deg[d4.x], 1);
        atomicAdd(&g_deg[d4.y], 1);
        atomicAdd(&g_deg[d4.z], 1);
        atomicAdd(&g_deg[d4.w], 1);
    } else {
        for (int k = i; k < e; k++) atomicAdd(&g_deg[dst[k]], 1);
    }
}

// Pass A: per-block exclusive scan of g_deg into g_off; block totals to g_bsum.
__global__ void k_scanA(int n) {
    int i    = blockIdx.x * SCAN_B + threadIdx.x;
    int lane = threadIdx.x & 31;
    int wid  = threadIdx.x >> 5;

    int v = (i < n) ? g_deg[i] : 0;
    int x = v;
    #pragma unroll
    for (int o = 1; o < 32; o <<= 1) {
        int t = __shfl_up_sync(0xffffffffu, x, o);
        if (lane >= o) x += t;
    }
    __shared__ int ws[8];
    if (lane == 31) ws[wid] = x;
    __syncthreads();
    if (wid == 0) {
        int y = (lane < 8) ? ws[lane] : 0;
        #pragma unroll
        for (int o = 1; o < 8; o <<= 1) {
            int t = __shfl_up_sync(0xffffffffu, y, o);
            if (lane >= o) y += t;
        }
        if (lane < 8) ws[lane] = y;
    }
    __syncthreads();
    int pre = (wid > 0) ? ws[wid - 1] : 0;
    int inc = x + pre;
    if (i < n) g_off[i] = inc - v;            // exclusive within block
    if (threadIdx.x == SCAN_B - 1) g_bsum[blockIdx.x] = inc;
}

// Pass B: one block scans NBLK block sums exclusively into g_boff.
__global__ void k_scanB(int nblk) {
    int t    = threadIdx.x;
    int lane = t & 31;
    int wid  = t >> 5;
    int v = (t < nblk) ? g_bsum[t] : 0;
    int x = v;
    #pragma unroll
    for (int o = 1; o < 32; o <<= 1) {
        int u = __shfl_up_sync(0xffffffffu, x, o);
        if (lane >= o) x += u;
    }
    __shared__ int ws[8];
    if (lane == 31) ws[wid] = x;
    __syncthreads();
    if (wid == 0) {
        int y = (lane < 8) ? ws[lane] : 0;
        #pragma unroll
        for (int o = 1; o < 8; o <<= 1) {
            int u = __shfl_up_sync(0xffffffffu, y, o);
            if (lane >= o) y += u;
        }
        if (lane < 8) ws[lane] = y;
    }
    __syncthreads();
    int pre = (wid > 0) ? ws[wid - 1] : 0;
    if (t < nblk) g_boff[t] = x + pre - v;    // exclusive
}

// Pass C: add block prefix; fill g_off/g_curp; g_off[n] = e.
__global__ void k_scanC(int n, int e) {
    int i = blockIdx.x * SCAN_B + threadIdx.x;
    if (i < n) {
        int o = g_off[i] + g_boff[blockIdx.x];
        g_off[i]  = o;
        g_curp[i] = o;
    }
    if (i == 0) g_off[n] = e;
}

// scatter + layer-0 edge weight, 4 edges per thread (batched loads, MLP=4).
// No max-subtraction: scores bounded, softmax shift-invariant.
__global__ void k_scatter_ex4(const int* __restrict__ src, const int* __restrict__ dst, int e) {
    int i = (blockIdx.x * blockDim.x + threadIdx.x) * 4;
    if (i + 3 < e) {
        int4 s4 = *(const int4*)(src + i);
        int4 d4 = *(const int4*)(dst + i);
        float ss0 = g_ssrc[s4.x], ss1 = g_ssrc[s4.y], ss2 = g_ssrc[s4.z], ss3 = g_ssrc[s4.w];
        float sd0 = g_sdst[d4.x], sd1 = g_sdst[d4.y], sd2 = g_sdst[d4.z], sd3 = g_sdst[d4.w];
        float a0 = ss0 + sd0, a1 = ss1 + sd1, a2 = ss2 + sd2, a3 = ss3 + sd3;
        float e0 = __expf((a0 > 0.f) ? a0 : NEG_SLOPE * a0);
        float e1 = __expf((a1 > 0.f) ? a1 : NEG_SLOPE * a1);
        float e2 = __expf((a2 > 0.f) ? a2 : NEG_SLOPE * a2);
        float e3 = __expf((a3 > 0.f) ? a3 : NEG_SLOPE * a3);
        int p0 = atomicAdd(&g_curp[d4.x], 1);
        int p1 = atomicAdd(&g_curp[d4.y], 1);
        int p2 = atomicAdd(&g_curp[d4.z], 1);
        int p3 = atomicAdd(&g_curp[d4.w], 1);
        g_ew[p0] = make_int2((int)((unsigned)s4.x | ((unsigned)d4.x << 16)), __float_as_int(e0));
        g_ew[p1] = make_int2((int)((unsigned)s4.y | ((unsigned)d4.y << 16)), __float_as_int(e1));
        g_ew[p2] = make_int2((int)((unsigned)s4.z | ((unsigned)d4.z << 16)), __float_as_int(e2));
        g_ew[p3] = make_int2((int)((unsigned)s4.w | ((unsigned)d4.w << 16)), __float_as_int(e3));
    } else {
        for (int k = i; k < e; k++) {
            int s = src[k], d = dst[k];
            float a  = g_ssrc[s] + g_sdst[d];
            float ev = (a > 0.f) ? a : NEG_SLOPE * a;
            int p = atomicAdd(&g_curp[d], 1);
            g_ew[p] = make_int2((int)((unsigned)s | ((unsigned)d << 16)), __float_as_int(__expf(ev)));
        }
    }
}

// ---------------- per-layer -----------------------------------------------------

// warp per node: fp32 h -> fp16 buffer A, layer-0 attention dots, zero g_deg.
__global__ void k_prep0(const float* __restrict__ h_ext, const float* __restrict__ w_row, int n) {
    int gid  = blockIdx.x * blockDim.x + threadIdx.x;
    int node = gid >> 5;
    int lane = threadIdx.x & 31;
    if (node >= n) return;

    float4 v = ((const float4*)h_ext)[node * 32 + lane];
    __half2 p01 = __floats2half2_rn(v.x, v.y);
    __half2 p23 = __floats2half2_rn(v.z, v.w);
    uint2 pk;
    pk.x = *(unsigned int*)&p01;
    pk.y = *(unsigned int*)&p23;
    g_hA[node * 32 + lane] = pk;

    float4 ws = ((const float4*)w_row)[lane];
    float4 wd = ((const float4*)w_row)[32 + lane];
    float ds = v.x * ws.x + v.y * ws.y + v.z * ws.z + v.w * ws.w;
    float dd = v.x * wd.x + v.y * wd.y + v.z * wd.z + v.w * wd.w;
    #pragma unroll
    for (int o = 16; o; o >>= 1) {
        ds += __shfl_xor_sync(0xffffffffu, ds, o);
        dd += __shfl_xor_sync(0xffffffffu, dd, o);
    }
    if (lane == 0) {
        g_ssrc[node] = ds;
        g_sdst[node] = dd;
        g_deg[node]  = 0;
    }
}

// per-edge layer-1 weight refresh, 2 records (one int4) per thread.
__global__ void k_w1(int e) {
    int i = (blockIdx.x * blockDim.x + threadIdx.x) * 2;
    if (i >= e) return;
    int4 q = __ldg((const int4*)(g_ew + i));
    unsigned p0 = (unsigned)q.x;
    unsigned p1 = (unsigned)q.z;
    float a0 = g_ssrc[p0 & 0xFFFFu] + g_sdst[p0 >> 16];
    float a1 = g_ssrc[p1 & 0xFFFFu] + g_sdst[p1 >> 16];
    q.y = __float_as_int(__expf((a0 > 0.f) ? a0 : NEG_SLOPE * a0));
    q.w = __float_as_int(__expf((a1 > 0.f) ? a1 : NEG_SLOPE * a1));
    *(int4*)(g_ew + i) = q;
}

// layer-0 aggregation: gather A -> fp16 B, with layer-1 dots fused in epilogue.
__global__ void k_agg0(const float* __restrict__ w_row, int n) {
    int gid  = blockIdx.x * blockDim.x + threadIdx.x;
    int node = gid >> 5;
    int lane = threadIdx.x & 31;
    if (node >= n) return;

    int beg = g_off[node];
    int end = g_off[node + 1];

    float4 acc = make_float4(0.f, 0.f, 0.f, 0.f);
    float  sum = 0.f;

    #pragma unroll 4
    for (int k = beg; k < end; k++) {
        int2 q = __ldg(&g_ew[k]);
        int s = (int)((unsigned)q.x & 0xFFFFu);
        float ex = __int_as_float(q.y);
        uint2 pk = __ldg(&g_hA[(size_t)s * 32 + lane]);
        float2 f01 = __half22float2(*(__half2*)&pk.x);
        float2 f23 = __half22float2(*(__half2*)&pk.y);
        acc.x = fmaf(f01.x, ex, acc.x);
        acc.y = fmaf(f01.y, ex, acc.y);
        acc.z = fmaf(f23.x, ex, acc.z);
        acc.w = fmaf(f23.y, ex, acc.w);
        sum  += ex;
    }

    float inv = (sum != 0.f) ? 1.f / sum : 0.f;
    acc.x *= inv; acc.y *= inv; acc.z *= inv; acc.w *= inv;

    __half2 p01 = __floats2half2_rn(acc.x, acc.y);
    __half2 p23 = __floats2half2_rn(acc.z, acc.w);
    uint2 pk;
    pk.x = *(unsigned int*)&p01;
    pk.y = *(unsigned int*)&p23;
    g_hB[node * 32 + lane] = pk;

    // fused layer-1 dots from the fp32 accumulator
    float4 ws = ((const float4*)w_row)[lane];
    float4 wd = ((const float4*)w_row)[32 + lane];
    float ds = acc.x * ws.x + acc.y * ws.y + acc.z * ws.z + acc.w * ws.w;
    float dd = acc.x * wd.x + acc.y * wd.y + acc.z * wd.z + acc.w * wd.w;
    #pragma unroll
    for (int o = 16; o; o >>= 1) {
        ds += __shfl_xor_sync(0xffffffffu, ds, o);
        dd += __shfl_xor_sync(0xffffffffu, dd, o);
    }
    if (lane == 0) {
        g_ssrc[node] = ds;
        g_sdst[node] = dd;
    }
}

// layer-1 aggregation: gather B -> fp32 out.
__global__ void k_agg1(float* __restrict__ out, int n) {
    int gid  = blockIdx.x * blockDim.x + threadIdx.x;
    int node = gid >> 5;
    int lane = threadIdx.x & 31;
    if (node >= n) return;

    int beg = g_off[node];
    int end = g_off[node + 1];

    float4 acc = make_float4(0.f, 0.f, 0.f, 0.f);
    float  sum = 0.f;

    #pragma unroll 4
    for (int k = beg; k < end; k++) {
        int2 q = __ldg(&g_ew[k]);
        int s = (int)((unsigned)q.x & 0xFFFFu);
        float ex = __int_as_float(q.y);
        uint2 pk = __ldg(&g_hB[(size_t)s * 32 + lane]);
        float2 f01 = __half22float2(*(__half2*)&pk.x);
        float2 f23 = __half22float2(*(__half2*)&pk.y);
        acc.x = fmaf(f01.x, ex, acc.x);
        acc.y = fmaf(f01.y, ex, acc.y);
        acc.z = fmaf(f23.x, ex, acc.z);
        acc.w = fmaf(f23.y, ex, acc.w);
        sum  += ex;
    }

    float inv = (sum != 0.f) ? 1.f / sum : 0.f;
    acc.x *= inv; acc.y *= inv; acc.z *= inv; acc.w *= inv;
    ((float4*)out)[node * 32 + lane] = acc;
}

// ---------------- launch --------------------------------------------------------

extern "C" void kernel_launch(void* const* d_in, const int* in_sizes, int n_in,
                              void* d_out, int out_size) {
    const float* h   = (const float*)d_in[0];
    const int*   src = (const int*)d_in[1];
    const int*   dst = (const int*)d_in[2];
    const float* att = (const float*)d_in[3];
    int n = in_sizes[0] / DD;
    int e = in_sizes[1];

    int node_blocks = (n * 32 + 255) / 256;
    int n_blocks    = (n + SCAN_B - 1) / SCAN_B;
    int e4_blocks   = ((e + 3) / 4 + 255) / 256;
    int e2_blocks   = ((e + 1) / 2 + 255) / 256;

    // layer-0 scalars + fp16 buffer A + deg reset
    k_prep0<<<node_blocks, 256>>>(h, att, n);

    // build dst-sorted packed edge list, layer-0 weights fused in
    k_hist4<<<e4_blocks, 256>>>(dst, e);
    k_scanA<<<n_blocks, SCAN_B>>>(n);
    k_scanB<<<1, SCAN_B>>>(n_blocks);
    k_scanC<<<n_blocks, SCAN_B>>>(n, e);
    k_scatter_ex4<<<e4_blocks, 256>>>(src, dst, e);

    // layer 0: gather A -> fp16 B (+ fused layer-1 dots)
    k_agg0<<<node_blocks, 256>>>(att + 2 * DD, n);

    // layer 1: refresh weights, gather B -> fp32 out
    k_w1<<<e2_blocks, 256>>>(e);
    k_agg1<<<node_blocks, 256>>>((float*)d_out, n);
}